// round 11
// baseline (speedup 1.0000x reference)
#include <cuda_runtime.h>
#include <cuda_bf16.h>
#include <cstdint>

#define NF    8192
#define NROWS 16384
#define EDIM  4096

__device__ float g_pool[NROWS * 90];
__device__ float g_emb[NROWS * 64];
__device__ float g_X[2 * NF * 256];
__device__ float g_H1[512 * 16 * 64];
__device__ float g_C1[512 * 16 * 64];
__device__ float g_H2[512 * 16 * 32];
__device__ float g_C2[512 * 16 * 32];
__device__ __nv_bfloat16 gA1h[(size_t)NROWS * 96];
__device__ __nv_bfloat16 gA1l[(size_t)NROWS * 96];
__device__ __nv_bfloat16 gW1h[(size_t)EDIM * 96];
__device__ __nv_bfloat16 gW1l[(size_t)EDIM * 96];
__device__ __nv_bfloat16 ghid_hi[(size_t)NROWS * EDIM];
__device__ __nv_bfloat16 ghid_lo[(size_t)NROWS * EDIM];
__device__ __nv_bfloat16 gB2h[64 * EDIM];
__device__ __nv_bfloat16 gB2l[64 * EDIM];

__device__ __forceinline__ uint32_t smem_to_u32(const void* p) {
    uint32_t a;
    asm("{ .reg .u64 t; cvta.to.shared.u64 t, %1; cvt.u32.u64 %0, t; }" : "=r"(a) : "l"(p));
    return a;
}
__device__ __forceinline__ void ldsm4(uint32_t* r, uint32_t addr) {
    asm volatile("ldmatrix.sync.aligned.m8n8.x4.shared.b16 {%0,%1,%2,%3}, [%4];"
                 : "=r"(r[0]), "=r"(r[1]), "=r"(r[2]), "=r"(r[3]) : "r"(addr));
}
__device__ __forceinline__ void mma_bf16(float* d, const uint32_t* a, const uint32_t* b) {
    asm volatile("mma.sync.aligned.m16n8k16.row.col.f32.bf16.bf16.f32 "
                 "{%0,%1,%2,%3}, {%4,%5,%6,%7}, {%8,%9}, {%0,%1,%2,%3};"
                 : "+f"(d[0]), "+f"(d[1]), "+f"(d[2]), "+f"(d[3])
                 : "r"(a[0]), "r"(a[1]), "r"(a[2]), "r"(a[3]), "r"(b[0]), "r"(b[1]));
}
__device__ __forceinline__ void cp_async16(uint32_t saddr, const void* g) {
    asm volatile("cp.async.cg.shared.global [%0], [%1], 16;" :: "r"(saddr), "l"(g));
}
#define CP_COMMIT() asm volatile("cp.async.commit_group;" ::: "memory")
__device__ __forceinline__ unsigned long long ffma2(unsigned long long a, unsigned long long b, unsigned long long c) {
    unsigned long long d;
    asm("fma.rn.f32x2 %0, %1, %2, %3;" : "=l"(d) : "l"(a), "l"(b), "l"(c));
    return d;
}
__device__ __forceinline__ unsigned long long pack2(float x) {
    unsigned long long d;
    unsigned int u = __float_as_uint(x);
    asm("mov.b64 %0, {%1, %1};" : "=l"(d) : "r"(u));
    return d;
}
__device__ __forceinline__ void unpack2(unsigned long long v, float& lo, float& hi) {
    unsigned int a, b;
    asm("mov.b64 {%0, %1}, %2;" : "=r"(a), "=r"(b) : "l"(v));
    lo = __uint_as_float(a);
    hi = __uint_as_float(b);
}
__device__ __forceinline__ float sigf(float x) { return 1.0f / (1.0f + __expf(-x)); }
__device__ __forceinline__ float tanh_f(float x) { return 1.0f - 2.0f / (__expf(2.0f * x) + 1.0f); }
__device__ __forceinline__ void split_bf16(float x, __nv_bfloat16& h, __nv_bfloat16& l) {
    h = __float2bfloat16(x);
    l = __float2bfloat16(x - __bfloat162float(h));
}

// ============== k_spp ==============
__global__ __launch_bounds__(256) void k_spp(const float* __restrict__ frames,
                                             const float* __restrict__ Wf,
                                             const float* __restrict__ bf,
                                             float* __restrict__ out_pooled,
                                             float* __restrict__ out_fpooled) {
    __shared__ float sF[3 * 48 * 48];
    __shared__ float sL4[48];
    __shared__ float sP[90];
    const int n = blockIdx.x, t = threadIdx.x;
    const float4* src = reinterpret_cast<const float4*>(frames + (size_t)n * 6912);
    float4* dst = reinterpret_cast<float4*>(sF);
    #pragma unroll
    for (int i = t; i < 1728; i += 256) dst[i] = src[i];
    __syncthreads();
    {
        int og = t >> 2, sub = t & 3;
        bool act = (og < 48);
        float m = -1e30f;
        if (act) {
            int c = og >> 4, rem = og & 15, i = rem >> 2, j = rem & 3;
            const float* base = sF + c * 2304 + (i * 12 + sub * 3) * 48 + j * 12;
            #pragma unroll
            for (int r = 0; r < 3; r++)
                #pragma unroll
                for (int q = 0; q < 12; q++) m = fmaxf(m, base[r * 48 + q]);
        }
        m = fmaxf(m, __shfl_xor_sync(0xffffffffu, m, 1));
        m = fmaxf(m, __shfl_xor_sync(0xffffffffu, m, 2));
        if (act && sub == 0) { sL4[og] = m; sP[og] = m; }
    }
    {
        int og = t >> 3, sub = t & 7;
        bool act = (og < 27);
        float m = -1e30f;
        if (act) {
            int c = og / 9, rem = og % 9, i = rem / 3, j = rem % 3;
            const float* base = sF + c * 2304 + (i * 16 + sub * 2) * 48 + j * 16;
            #pragma unroll
            for (int r = 0; r < 2; r++)
                #pragma unroll
                for (int q = 0; q < 16; q++) m = fmaxf(m, base[r * 48 + q]);
        }
        m = fmaxf(m, __shfl_xor_sync(0xffffffffu, m, 1));
        m = fmaxf(m, __shfl_xor_sync(0xffffffffu, m, 2));
        m = fmaxf(m, __shfl_xor_sync(0xffffffffu, m, 4));
        if (act && sub == 0) sP[48 + og] = m;
    }
    __syncthreads();
    if (t < 12) {
        int c = t >> 2, rem = t & 3, i = rem >> 1, j = rem & 1;
        const float* L = sL4 + c * 16;
        float m = fmaxf(fmaxf(L[(2 * i) * 4 + 2 * j], L[(2 * i) * 4 + 2 * j + 1]),
                        fmaxf(L[(2 * i + 1) * 4 + 2 * j], L[(2 * i + 1) * 4 + 2 * j + 1]));
        sP[75 + t] = m;
    } else if (t < 15) {
        int c = t - 12;
        float m = -1e30f;
        #pragma unroll
        for (int q = 0; q < 16; q++) m = fmaxf(m, sL4[c * 16 + q]);
        sP[87 + c] = m;
    }
    __syncthreads();
    if (t < 90) {
        float v = sP[t];
        out_pooled[(size_t)n * 90 + t] = v;
        g_pool[(size_t)n * 90 + t] = v;
        float a0 = bf[t], a1 = 0.f;
        const float* wr = Wf + t * 90;
        #pragma unroll
        for (int k = 0; k < 90; k += 2) {
            a0 = fmaf(sP[k], wr[k], a0);
            a1 = fmaf(sP[k + 1], wr[k + 1], a1);
        }
        float acc = a0 + a1;
        out_fpooled[(size_t)n * 90 + t] = acc;
        g_pool[(size_t)(NF + n) * 90 + t] = acc;
    }
}

// ============== prep kernels ==============
__global__ __launch_bounds__(256) void k_prepA() {
    int r = blockIdx.x * 8 + (threadIdx.x >> 5);
    int lane = threadIdx.x & 31;
    const float* src = g_pool + (size_t)r * 90;
    #pragma unroll
    for (int it = 0; it < 3; it++) {
        int k = it * 32 + lane;
        float x = (k < 90) ? src[k] : 0.f;
        __nv_bfloat16 h, l;
        split_bf16(x, h, l);
        gA1h[(size_t)r * 96 + k] = h;
        gA1l[(size_t)r * 96 + k] = l;
    }
}
__global__ __launch_bounds__(256) void k_prepW1(const float* __restrict__ W1) {
    int r = blockIdx.x * 8 + (threadIdx.x >> 5);
    int lane = threadIdx.x & 31;
    const float* src = W1 + (size_t)r * 90;
    #pragma unroll
    for (int it = 0; it < 3; it++) {
        int k = it * 32 + lane;
        float x = (k < 90) ? src[k] : 0.f;
        __nv_bfloat16 h, l;
        split_bf16(x, h, l);
        gW1h[(size_t)r * 96 + k] = h;
        gW1l[(size_t)r * 96 + k] = l;
    }
}
__global__ __launch_bounds__(256) void k_prepB2(const float* __restrict__ F) {
    for (int i = blockIdx.x * 256 + threadIdx.x; i < 64 * EDIM; i += gridDim.x * 256) {
        __nv_bfloat16 h, l;
        split_bf16(F[i], h, l);
        gB2h[i] = h;
        gB2l[i] = l;
    }
}

// ============== GEMM1: hid = relu(P@W1^T + b1) -> bf16 hi/lo  (2 CTAs/SM) ==============
#define G1_LDA 104
#define G1_SMEM (4 * 128 * G1_LDA * 2)
__global__ __launch_bounds__(256, 2) void k_g1(const float* __restrict__ b1) {
    extern __shared__ __align__(16) char sm1[];
    __nv_bfloat16* sAhi = (__nv_bfloat16*)sm1;
    __nv_bfloat16* sAlo = sAhi + 128 * G1_LDA;
    __nv_bfloat16* sBhi = sAlo + 128 * G1_LDA;
    __nv_bfloat16* sBlo = sBhi + 128 * G1_LDA;
    __shared__ float sBias[128];
    const int t = threadIdx.x, lane = t & 31, wid = t >> 5;
    const int rb = blockIdx.y * 128, jb = blockIdx.x * 128;

    if (t < 128) sBias[t] = b1[jb + t];
    #pragma unroll
    for (int i = t; i < 1536; i += 256) {
        int r = i / 12, c8 = (i % 12) * 8;
        *(uint4*)(sAhi + r * G1_LDA + c8) = *(const uint4*)(gA1h + (size_t)(rb + r) * 96 + c8);
        *(uint4*)(sAlo + r * G1_LDA + c8) = *(const uint4*)(gA1l + (size_t)(rb + r) * 96 + c8);
        *(uint4*)(sBhi + r * G1_LDA + c8) = *(const uint4*)(gW1h + (size_t)(jb + r) * 96 + c8);
        *(uint4*)(sBlo + r * G1_LDA + c8) = *(const uint4*)(gW1l + (size_t)(jb + r) * 96 + c8);
    }
    __syncthreads();

    const int wm = wid >> 1, wn = wid & 1;
    float acc[2][8][4];
    #pragma unroll
    for (int mi = 0; mi < 2; mi++)
        #pragma unroll
        for (int nt = 0; nt < 8; nt++)
            #pragma unroll
            for (int q = 0; q < 4; q++) acc[mi][nt][q] = 0.f;

    const uint32_t uAhi = smem_to_u32(sAhi), uAlo = smem_to_u32(sAlo);
    const uint32_t uBhi = smem_to_u32(sBhi), uBlo = smem_to_u32(sBlo);
    const int j = lane >> 3;
    const uint32_t aRowOff = (uint32_t)((wm * 32 + (lane & 15)) * G1_LDA + ((lane >> 4) << 3)) * 2;
    const uint32_t bRowOff = (uint32_t)((wn * 64 + ((j >> 1) << 3) + (lane & 7)) * G1_LDA + ((j & 1) << 3)) * 2;

    #pragma unroll
    for (int pass = 0; pass < 3; pass++) {
        const uint32_t aBase = ((pass == 1) ? uAlo : uAhi) + aRowOff;
        const uint32_t bBase = ((pass == 2) ? uBlo : uBhi) + bRowOff;
        #pragma unroll
        for (int kk = 0; kk < 6; kk++) {
            uint32_t a[2][4];
            ldsm4(a[0], aBase + kk * 32);
            ldsm4(a[1], aBase + (16 * G1_LDA * 2) + kk * 32);
            #pragma unroll
            for (int nt2 = 0; nt2 < 4; nt2++) {
                uint32_t b[4];
                ldsm4(b, bBase + (uint32_t)(nt2 * 16 * G1_LDA * 2) + kk * 32);
                mma_bf16(acc[0][nt2 * 2],     a[0], b);
                mma_bf16(acc[0][nt2 * 2 + 1], a[0], b + 2);
                mma_bf16(acc[1][nt2 * 2],     a[1], b);
                mma_bf16(acc[1][nt2 * 2 + 1], a[1], b + 2);
            }
        }
    }
    __syncthreads();

    float* stage = (float*)sm1;   // [128][132]
    const int g = lane >> 2, i2 = (lane & 3) * 2;
    #pragma unroll
    for (int mi = 0; mi < 2; mi++)
        #pragma unroll
        for (int nt = 0; nt < 8; nt++) {
            int row = wm * 32 + mi * 16 + g;
            int col = wn * 64 + nt * 8 + i2;
            stage[row * 132 + col]           = fmaxf(acc[mi][nt][0] + sBias[col], 0.f);
            stage[row * 132 + col + 1]       = fmaxf(acc[mi][nt][1] + sBias[col + 1], 0.f);
            stage[(row + 8) * 132 + col]     = fmaxf(acc[mi][nt][2] + sBias[col], 0.f);
            stage[(row + 8) * 132 + col + 1] = fmaxf(acc[mi][nt][3] + sBias[col + 1], 0.f);
        }
    __syncthreads();
    for (int i = t; i < 2048; i += 256) {
        int r = i >> 4, c8 = (i & 15) << 3;
        __nv_bfloat16 hb[8], lb[8];
        #pragma unroll
        for (int jj2 = 0; jj2 < 8; jj2++) split_bf16(stage[r * 132 + c8 + jj2], hb[jj2], lb[jj2]);
        size_t gi = (size_t)(rb + r) * EDIM + jb + c8;
        *(uint4*)(ghid_hi + gi) = *(uint4*)hb;
        *(uint4*)(ghid_lo + gi) = *(uint4*)lb;
    }
}

// ============== GEMM2: emb = relu(hid@fc7^T + b7)  (K-chunk 64, 2 CTAs/SM) ==============
#define G2_LDA 72
#define G2_BUF 55296        // Ahi 18432 + Alo 18432 + Bhi 9216 + Blo 9216
#define G2_SMEM (2 * G2_BUF)
__global__ __launch_bounds__(256, 2) void k_g2(const float* __restrict__ b7) {
    extern __shared__ __align__(16) char sm2[];
    __shared__ float sBias[64];
    const int t = threadIdx.x, lane = t & 31, wid = t >> 5;
    const int rb = blockIdx.x * 128;
    if (t < 64) sBias[t] = b7[t];

    const uint32_t ubase = smem_to_u32(sm2);
    const int wm = wid >> 1, wn = wid & 1;
    float acc[2][4][4];
    #pragma unroll
    for (int mi = 0; mi < 2; mi++)
        #pragma unroll
        for (int nt = 0; nt < 4; nt++)
            #pragma unroll
            for (int q = 0; q < 4; q++) acc[mi][nt][q] = 0.f;

    const int j = lane >> 3;
    const uint32_t aRowOff = (uint32_t)((wm * 32 + (lane & 15)) * G2_LDA + ((lane >> 4) << 3)) * 2;
    const uint32_t bRowOff = (uint32_t)((wn * 32 + ((j >> 1) << 3) + (lane & 7)) * G2_LDA + ((j & 1) << 3)) * 2;

    // loader: 12 cp.async16 per thread per chunk (K-chunk = 64)
    auto load_chunk = [&](int c, int buf) {
        const int kc = c << 6;
        const uint32_t bb = ubase + buf * G2_BUF;
        #pragma unroll
        for (int i = t; i < 2048; i += 256) {
            int arr = i >> 10, idx = i & 1023;
            int r = idx >> 3, c8 = (idx & 7) << 3;
            const __nv_bfloat16* g = (arr ? ghid_lo : ghid_hi) + (size_t)(rb + r) * EDIM + kc + c8;
            cp_async16(bb + (uint32_t)(arr * 18432) + (uint32_t)(r * G2_LDA + c8) * 2, g);
        }
        #pragma unroll
        for (int i = t; i < 1024; i += 256) {
            int arr = i >> 9, idx = i & 511;
            int n = idx >> 3, c8 = (idx & 7) << 3;
            const __nv_bfloat16* g = (arr ? gB2l : gB2h) + (size_t)n * EDIM + kc + c8;
            cp_async16(bb + 36864u + (uint32_t)(arr * 9216) + (uint32_t)(n * G2_LDA + c8) * 2, g);
        }
    };

    load_chunk(0, 0);
    CP_COMMIT();

    for (int c = 0; c < 64; c++) {
        if (c + 1 < 64) {
            load_chunk(c + 1, (c + 1) & 1);
            CP_COMMIT();
            asm volatile("cp.async.wait_group 1;" ::: "memory");
        } else {
            asm volatile("cp.async.wait_group 0;" ::: "memory");
        }
        __syncthreads();
        const uint32_t bb = ubase + (c & 1) * G2_BUF;
        const uint32_t uAhi = bb, uAlo = bb + 18432u, uBhi = bb + 36864u, uBlo = bb + 46080u;
        #pragma unroll
        for (int pass = 0; pass < 3; pass++) {
            const uint32_t aBase = ((pass == 1) ? uAlo : uAhi) + aRowOff;
            const uint32_t bBase = ((pass == 2) ? uBlo : uBhi) + bRowOff;
            #pragma unroll
            for (int kk = 0; kk < 4; kk++) {
                uint32_t a[2][4];
                ldsm4(a[0], aBase + kk * 32);
                ldsm4(a[1], aBase + (16 * G2_LDA * 2) + kk * 32);
                #pragma unroll
                for (int nt2 = 0; nt2 < 2; nt2++) {
                    uint32_t b[4];
                    ldsm4(b, bBase + (uint32_t)(nt2 * 16 * G2_LDA * 2) + kk * 32);
                    mma_bf16(acc[0][nt2 * 2],     a[0], b);
                    mma_bf16(acc[0][nt2 * 2 + 1], a[0], b + 2);
                    mma_bf16(acc[1][nt2 * 2],     a[1], b);
                    mma_bf16(acc[1][nt2 * 2 + 1], a[1], b + 2);
                }
            }
        }
        __syncthreads();
    }

    float* stage = (float*)sm2;   // [128][68]
    const int g = lane >> 2, i2 = (lane & 3) * 2;
    #pragma unroll
    for (int mi = 0; mi < 2; mi++)
        #pragma unroll
        for (int nt = 0; nt < 4; nt++) {
            int row = wm * 32 + mi * 16 + g;
            int col = wn * 32 + nt * 8 + i2;
            stage[row * 68 + col]           = fmaxf(acc[mi][nt][0] + sBias[col], 0.f);
            stage[row * 68 + col + 1]       = fmaxf(acc[mi][nt][1] + sBias[col + 1], 0.f);
            stage[(row + 8) * 68 + col]     = fmaxf(acc[mi][nt][2] + sBias[col], 0.f);
            stage[(row + 8) * 68 + col + 1] = fmaxf(acc[mi][nt][3] + sBias[col + 1], 0.f);
        }
    __syncthreads();
    for (int i = t; i < 2048; i += 256) {
        int r = i >> 4, c4 = (i & 15) << 2;
        *(float4*)&g_emb[(size_t)(rb + r) * 64 + c4] = *(float4*)&stage[r * 68 + c4];
    }
}

// ============== k_x (unchanged) ==============
__global__ __launch_bounds__(256) void k_x(const float* __restrict__ wih,
                                           const float* __restrict__ bih,
                                           const float* __restrict__ bhh) {
    extern __shared__ float smx[];
    float* sAT = smx;
    float* sWT = smx + 64 * 68;
    const int t = threadIdx.x;
    const int rb = blockIdx.y * 64;
    const int jb = blockIdx.x * 128;
    #pragma unroll
    for (int i = t; i < 1024; i += 256) {
        int q = i >> 6, r = i & 63;
        float4 v = *reinterpret_cast<const float4*>(&g_emb[(size_t)(rb + r) * 64 + q * 4]);
        sAT[(q * 4 + 0) * 68 + r] = v.x;
        sAT[(q * 4 + 1) * 68 + r] = v.y;
        sAT[(q * 4 + 2) * 68 + r] = v.z;
        sAT[(q * 4 + 3) * 68 + r] = v.w;
    }
    #pragma unroll
    for (int i = t; i < 2048; i += 256) {
        int kq = i >> 7, j = i & 127;
        float4 v = *reinterpret_cast<const float4*>(&wih[(size_t)(jb + j) * 64 + kq * 4]);
        sWT[(kq * 4 + 0) * 128 + j] = v.x;
        sWT[(kq * 4 + 1) * 128 + j] = v.y;
        sWT[(kq * 4 + 2) * 128 + j] = v.z;
        sWT[(kq * 4 + 3) * 128 + j] = v.w;
    }
    __syncthreads();
    const int jj = t & 31, rr = t >> 5;
    const int j = jj * 4, r0 = rr * 8;
    unsigned long long acc[4][4];
    #pragma unroll
    for (int p = 0; p < 4; p++)
        #pragma unroll
        for (int q = 0; q < 4; q++) acc[p][q] = 0ULL;
    #pragma unroll 16
    for (int k = 0; k < 64; k++) {
        const ulonglong2* pa = reinterpret_cast<const ulonglong2*>(sAT + k * 68 + r0);
        ulonglong2 a01 = pa[0], a23 = pa[1];
        unsigned long long a[4] = {a01.x, a01.y, a23.x, a23.y};
        float4 wv = *reinterpret_cast<const float4*>(sWT + k * 128 + j);
        unsigned long long w[4] = {pack2(wv.x), pack2(wv.y), pack2(wv.z), pack2(wv.w)};
        #pragma unroll
        for (int p = 0; p < 4; p++)
            #pragma unroll
            for (int q = 0; q < 4; q++) acc[p][q] = ffma2(a[p], w[q], acc[p][q]);
    }
    float4 bi = *reinterpret_cast<const float4*>(&bih[jb + j]);
    float4 bh = *reinterpret_cast<const float4*>(&bhh[jb + j]);
    float4 bv = make_float4(bi.x + bh.x, bi.y + bh.y, bi.z + bh.z, bi.w + bh.w);
    #pragma unroll
    for (int p = 0; p < 4; p++) {
        float x0, y0, x1, y1, x2, y2, x3, y3;
        unpack2(acc[p][0], x0, y0);
        unpack2(acc[p][1], x1, y1);
        unpack2(acc[p][2], x2, y2);
        unpack2(acc[p][3], x3, y3);
        float4 rA = make_float4(x0 + bv.x, x1 + bv.y, x2 + bv.z, x3 + bv.w);
        float4 rB = make_float4(y0 + bv.x, y1 + bv.y, y2 + bv.z, y3 + bv.w);
        int rowA = rb + r0 + 2 * p;
        int rowB = rowA + 1;
        {
            int branch = rowA >> 13, n = rowA & 8191, b = n >> 9, s = n & 511;
            size_t dst = ((size_t)branch * NF + (size_t)s * 16 + b) * 256 + jb + j;
            *reinterpret_cast<float4*>(&g_X[dst]) = rA;
        }
        {
            int branch = rowB >> 13, n = rowB & 8191, b = n >> 9, s = n & 511;
            size_t dst = ((size_t)branch * NF + (size_t)s * 16 + b) * 256 + jb + j;
            *reinterpret_cast<float4*>(&g_X[dst]) = rB;
        }
    }
}

// ============== k_lstm (quad-gate mapping, 2 syncs/step) ==============
__global__ __launch_bounds__(256) void k_lstm(const float* __restrict__ whh1,
                                              const float* __restrict__ wih2,
                                              const float* __restrict__ whh2,
                                              const float* __restrict__ bih2,
                                              const float* __restrict__ bhh2) {
    __shared__ __align__(16) float sxin[192];
    const int b = blockIdx.x, t = threadIdx.x;
    const int u = t >> 2, q = t & 3;
    const int gi = q * 64 + u;

    float w1[64];
    #pragma unroll
    for (int k = 0; k < 64; k++) w1[k] = whh1[gi * 64 + k];

    const int v = (t >> 2) & 31;
    const int gi2 = q * 32 + v;
    float w2i[64], w2h[32];
    float b2 = 0.f;
    if (t < 128) {
        #pragma unroll
        for (int k = 0; k < 64; k++) w2i[k] = wih2[gi2 * 64 + k];
        #pragma unroll
        for (int k = 0; k < 32; k++) w2h[k] = whh2[gi2 * 32 + k];
        b2 = bih2[gi2] + bhh2[gi2];
    }

    float c1 = 0.f, c2 = 0.f;
    if (t < 192) sxin[t] = 0.f;
    __syncthreads();

    const float* xbase = g_X + (size_t)b * 256;
    float xg = xbase[gi];
    const int lanebase = t & ~3;

    for (int s = 0; s < 512; s++) {
        float xn = (s < 511) ? xbase[(size_t)(s + 1) * 4096 + gi] : 0.f;
        const int p = s & 1;
        const float4* h1rd = (const float4*)(sxin + 64 * p);
        const float4* h1nw = (const float4*)(sxin + 64 * (1 - p));
        const float4* h2rd = (const float4*)(sxin + 128 + 32 * p);

        float a0 = xg, a1 = 0.f, a2 = 0.f, a3 = 0.f;
        #pragma unroll
        for (int k = 0; k < 16; k++) {
            float4 hv = h1rd[k];
            a0 = fmaf(hv.x, w1[4 * k],     a0);
            a1 = fmaf(hv.y, w1[4 * k + 1], a1);
            a2 = fmaf(hv.z, w1[4 * k + 2], a2);
            a3 = fmaf(hv.w, w1[4 * k + 3], a3);
        }
        float av = (a0 + a1) + (a2 + a3);
        float gv = (q == 2) ? tanh_f(av) : sigf(av);
        float vi = __shfl_sync(0xffffffffu, gv, lanebase);
        float vf = __shfl_sync(0xffffffffu, gv, lanebase + 1);
        float vg = __shfl_sync(0xffffffffu, gv, lanebase + 2);
        float vo = __shfl_sync(0xffffffffu, gv, lanebase + 3);
        if (q == 0) {
            c1 = vf * c1 + vi * vg;
            float h1v = vo * tanh_f(c1);
            sxin[64 * (1 - p) + u] = h1v;
            g_H1[((size_t)s * 16 + b) * 64 + u] = h1v;
            g_C1[((size_t)s * 16 + b) * 64 + u] = c1;
        }
        __syncthreads();

        if (t < 128) {
            float p0 = b2, p1 = 0.f, p2 = 0.f, p3 = 0.f;
            #pragma unroll
            for (int k = 0; k < 16; k++) {
                float4 hv = h1nw[k];
                p0 = fmaf(hv.x, w2i[4 * k],     p0);
                p1 = fmaf(hv.y, w2i[4 * k + 1], p1);
                p2 = fmaf(hv.z, w2i[4 * k + 2], p2);
                p3 = fmaf(hv.w, w2i[4 * k + 3], p3);
            }
            #pragma unroll
            for (int k = 0; k < 8; k++) {
                float4 hv = h2rd[k];
                p0 = fmaf(hv.x, w2h[4 * k],     p0);
                p1 = fmaf(hv.y, w2h[4 * k + 1], p1);
                p2 = fmaf(hv.z, w2h[4 * k + 2], p2);
                p3 = fmaf(hv.w, w2h[4 * k + 3], p3);
            }
            float pv = (p0 + p1) + (p2 + p3);
            float g2v = (q == 2) ? tanh_f(pv) : sigf(pv);
            float wi = __shfl_sync(0xffffffffu, g2v, lanebase);
            float wf = __shfl_sync(0xffffffffu, g2v, lanebase + 1);
            float wg = __shfl_sync(0xffffffffu, g2v, lanebase + 2);
            float wo = __shfl_sync(0xffffffffu, g2v, lanebase + 3);
            if (q == 0) {
                c2 = wf * c2 + wi * wg;
                float h2v = wo * tanh_f(c2);
                sxin[128 + 32 * (1 - p) + v] = h2v;
                g_H2[((size_t)s * 16 + b) * 32 + v] = h2v;
                g_C2[((size_t)s * 16 + b) * 32 + v] = c2;
            }
        }
        xg = xn;
        __syncthreads();
    }
}

// ============== k_f (unchanged) ==============
__global__ __launch_bounds__(256) void k_f(const float* __restrict__ whh1,
                                           const float* __restrict__ wih2,
                                           const float* __restrict__ whh2,
                                           const float* __restrict__ bih2,
                                           const float* __restrict__ bhh2,
                                           const float* __restrict__ fc8w,
                                           const float* __restrict__ fc8b,
                                           float* __restrict__ out_prog,
                                           float* __restrict__ out_fprog) {
    extern __shared__ float smf[];
    float* w1T  = smf;
    float* wi2T = w1T + 64 * 256;
    float* wh2T = wi2T + 64 * 128;
    float* b2s  = wh2T + 32 * 128;
    float* sH1  = b2s + 128;
    float* sC1  = sH1 + 1024;
    float* sH2  = sC1 + 1024;
    float* sC2  = sH2 + 512;
    float* sG1  = sC2 + 512;
    float* sFh1 = sG1 + 4096;
    float* sG2  = sFh1 + 1024;
    float* sFh2 = sG2 + 2048;
    const int t = threadIdx.x;
    const int s = blockIdx.x;
    const size_t r0 = (size_t)s * 16;
    for (int i = t; i < 64 * 256; i += 256) {
        int k = i >> 8, g = i & 255;
        w1T[i] = whh1[g * 64 + k];
    }
    for (int i = t; i < 64 * 128; i += 256) {
        int k = i >> 7, g = i & 127;
        wi2T[i] = wih2[g * 64 + k];
    }
    for (int i = t; i < 32 * 128; i += 256) {
        int k = i >> 7, g = i & 127;
        wh2T[i] = whh2[g * 32 + k];
    }
    if (t < 128) b2s[t] = bih2[t] + bhh2[t];
    for (int i = t; i < 1024; i += 256) sH1[i] = g_H1[r0 * 64 + i];
    for (int i = t; i < 1024; i += 256) sC1[i] = g_C1[r0 * 64 + i];
    for (int i = t; i < 512;  i += 256) sH2[i] = g_H2[r0 * 32 + i];
    for (int i = t; i < 512;  i += 256) sC2[i] = g_C2[r0 * 32 + i];
    for (int i = t; i < 4096; i += 256) sG1[i] = g_X[(size_t)NF * 256 + r0 * 256 + i];
    __syncthreads();
    {
        float acc[16];
        #pragma unroll
        for (int r = 0; r < 16; r++) acc[r] = sG1[r * 256 + t];
        #pragma unroll 8
        for (int k = 0; k < 64; k++) {
            float w = w1T[k * 256 + t];
            #pragma unroll
            for (int r = 0; r < 16; r++) acc[r] = fmaf(sH1[r * 64 + k], w, acc[r]);
        }
        bool is_g = ((t >> 6) == 2);
        #pragma unroll
        for (int r = 0; r < 16; r++)
            sG1[r * 256 + t] = is_g ? tanhf(acc[r]) : sigf(acc[r]);
    }
    __syncthreads();
    for (int i = t; i < 1024; i += 256) {
        int r = i >> 6, u = i & 63;
        const float* g = sG1 + r * 256;
        float c = g[64 + u] * sC1[r * 64 + u] + g[u] * g[128 + u];
        sFh1[r * 64 + u] = g[192 + u] * tanhf(c);
    }
    __syncthreads();
    if (t < 128) {
        float acc[16];
        #pragma unroll
        for (int r = 0; r < 16; r++) acc[r] = b2s[t];
        #pragma unroll 8
        for (int k = 0; k < 64; k++) {
            float w = wi2T[k * 128 + t];
            #pragma unroll
            for (int r = 0; r < 16; r++) acc[r] = fmaf(sFh1[r * 64 + k], w, acc[r]);
        }
        #pragma unroll 8
        for (int k = 0; k < 32; k++) {
            float w = wh2T[k * 128 + t];
            #pragma unroll
            for (int r = 0; r < 16; r++) acc[r] = fmaf(sH2[r * 32 + k], w, acc[r]);
        }
        bool is_g = ((t >> 5) == 2);
        #pragma unroll
        for (int r = 0; r < 16; r++)
            sG2[r * 128 + t] = is_g ? tanhf(acc[r]) : sigf(acc[r]);
    }
    __syncthreads();
    for (int i = t; i < 512; i += 256) {
        int r = i >> 5, u = i & 31;
        const float* g = sG2 + r * 128;
        float c = g[32 + u] * sC2[r * 32 + u] + g[u] * g[64 + u];
        sFh2[r * 32 + u] = g[96 + u] * tanhf(c);
    }
    __syncthreads();
    if (t < 32) {
        int r = t >> 1, which = t & 1;
        const float* v = which ? (sFh2 + r * 32) : (sH2 + r * 32);
        float acc = fc8b[0];
        #pragma unroll
        for (int k = 0; k < 32; k++) acc = fmaf(v[k], fc8w[k], acc);
        float ov = sigf(acc);
        int b = r;
        if (which) out_fprog[(size_t)b * 512 + s] = ov;
        else       out_prog[(size_t)b * 512 + s] = ov;
    }
}

// =====================================================================
extern "C" void kernel_launch(void* const* d_in, const int* in_sizes, int n_in,
                              void* d_out, int out_size) {
    const float* frames  = (const float*)d_in[0];
    const float* spp_w   = (const float*)d_in[1];
    const float* spp_b   = (const float*)d_in[2];
    const float* fore_w  = (const float*)d_in[3];
    const float* fore_b  = (const float*)d_in[4];
    const float* fc7_w   = (const float*)d_in[5];
    const float* fc7_b   = (const float*)d_in[6];
    const float* l1_wih  = (const float*)d_in[7];
    const float* l1_whh  = (const float*)d_in[8];
    const float* l1_bih  = (const float*)d_in[9];
    const float* l1_bhh  = (const float*)d_in[10];
    const float* l2_wih  = (const float*)d_in[11];
    const float* l2_whh  = (const float*)d_in[12];
    const float* l2_bih  = (const float*)d_in[13];
    const float* l2_bhh  = (const float*)d_in[14];
    const float* fc8_w   = (const float*)d_in[15];
    const float* fc8_b   = (const float*)d_in[16];

    float* out         = (float*)d_out;
    float* out_prog    = out;
    float* out_fprog   = out + 8192;
    float* out_pooled  = out + 16384;
    float* out_fpooled = out + 16384 + 737280;

    const int smem_x = (64 * 68 + 64 * 128) * 4;
    const int smem_f = (64 * 256 + 64 * 128 + 32 * 128 + 128 +
                        1024 + 1024 + 512 + 512 + 4096 + 1024 + 2048 + 512) * 4;
    cudaFuncSetAttribute(k_g1, cudaFuncAttributeMaxDynamicSharedMemorySize, G1_SMEM);
    cudaFuncSetAttribute(k_g2, cudaFuncAttributeMaxDynamicSharedMemorySize, G2_SMEM);
    cudaFuncSetAttribute(k_x,  cudaFuncAttributeMaxDynamicSharedMemorySize, smem_x);
    cudaFuncSetAttribute(k_f,  cudaFuncAttributeMaxDynamicSharedMemorySize, smem_f);

    k_spp<<<NF, 256>>>(frames, fore_w, fore_b, out_pooled, out_fpooled);
    k_prepA<<<NROWS / 8, 256>>>();
    k_prepW1<<<EDIM / 8, 256>>>(spp_w);
    k_prepB2<<<64, 256>>>(fc7_w);
    k_g1<<<dim3(32, 128), 256, G1_SMEM>>>(spp_b);
    k_g2<<<128, 256, G2_SMEM>>>(fc7_b);
    k_x<<<dim3(2, 256), 256, smem_x>>>(l1_wih, l1_bih, l1_bhh);
    k_lstm<<<16, 256>>>(l1_whh, l2_wih, l2_whh, l2_bih, l2_bhh);
    k_f<<<512, 256, smem_f>>>(l1_whh, l2_wih, l2_whh, l2_bih, l2_bhh, fc8_w, fc8_b,
                              out_prog, out_fprog);
}

// round 12
// speedup vs baseline: 1.1722x; 1.1722x over previous
#include <cuda_runtime.h>
#include <cuda_bf16.h>
#include <cstdint>

#define NF    8192
#define NROWS 16384
#define EDIM  4096

__device__ float g_emb[NROWS * 64];
__device__ float g_X[2 * NF * 256];
__device__ float g_H1[512 * 16 * 64];
__device__ float g_C1[512 * 16 * 64];
__device__ float g_H2[512 * 16 * 32];
__device__ float g_C2[512 * 16 * 32];
__device__ __nv_bfloat16 gA1h[(size_t)NROWS * 96];
__device__ __nv_bfloat16 gA1l[(size_t)NROWS * 96];
__device__ __nv_bfloat16 gW1h[(size_t)EDIM * 96];
__device__ __nv_bfloat16 gW1l[(size_t)EDIM * 96];
__device__ __nv_bfloat16 ghid_hi[(size_t)NROWS * EDIM];
__device__ __nv_bfloat16 ghid_lo[(size_t)NROWS * EDIM];
__device__ __nv_bfloat16 gB2h[64 * EDIM];
__device__ __nv_bfloat16 gB2l[64 * EDIM];

__device__ __forceinline__ uint32_t smem_to_u32(const void* p) {
    uint32_t a;
    asm("{ .reg .u64 t; cvta.to.shared.u64 t, %1; cvt.u32.u64 %0, t; }" : "=r"(a) : "l"(p));
    return a;
}
__device__ __forceinline__ void ldsm4(uint32_t* r, uint32_t addr) {
    asm volatile("ldmatrix.sync.aligned.m8n8.x4.shared.b16 {%0,%1,%2,%3}, [%4];"
                 : "=r"(r[0]), "=r"(r[1]), "=r"(r[2]), "=r"(r[3]) : "r"(addr));
}
__device__ __forceinline__ void mma_bf16(float* d, const uint32_t* a, const uint32_t* b) {
    asm volatile("mma.sync.aligned.m16n8k16.row.col.f32.bf16.bf16.f32 "
                 "{%0,%1,%2,%3}, {%4,%5,%6,%7}, {%8,%9}, {%0,%1,%2,%3};"
                 : "+f"(d[0]), "+f"(d[1]), "+f"(d[2]), "+f"(d[3])
                 : "r"(a[0]), "r"(a[1]), "r"(a[2]), "r"(a[3]), "r"(b[0]), "r"(b[1]));
}
__device__ __forceinline__ void cp_async16(uint32_t saddr, const void* g) {
    asm volatile("cp.async.cg.shared.global [%0], [%1], 16;" :: "r"(saddr), "l"(g));
}
#define CP_COMMIT() asm volatile("cp.async.commit_group;" ::: "memory")
__device__ __forceinline__ unsigned long long ffma2(unsigned long long a, unsigned long long b, unsigned long long c) {
    unsigned long long d;
    asm("fma.rn.f32x2 %0, %1, %2, %3;" : "=l"(d) : "l"(a), "l"(b), "l"(c));
    return d;
}
__device__ __forceinline__ unsigned long long pack2(float x) {
    unsigned long long d;
    unsigned int u = __float_as_uint(x);
    asm("mov.b64 %0, {%1, %1};" : "=l"(d) : "r"(u));
    return d;
}
__device__ __forceinline__ void unpack2(unsigned long long v, float& lo, float& hi) {
    unsigned int a, b;
    asm("mov.b64 {%0, %1}, %2;" : "=r"(a), "=r"(b) : "l"(v));
    lo = __uint_as_float(a);
    hi = __uint_as_float(b);
}
__device__ __forceinline__ float sigf(float x) { return 1.0f / (1.0f + __expf(-x)); }
__device__ __forceinline__ float tanh_f(float x) { return 1.0f - 2.0f / (__expf(2.0f * x) + 1.0f); }
__device__ __forceinline__ void split_bf16(float x, __nv_bfloat16& h, __nv_bfloat16& l) {
    h = __float2bfloat16(x);
    l = __float2bfloat16(x - __bfloat162float(h));
}

// ============== k_spp (now also emits gA1 hi/lo split directly) ==============
__global__ __launch_bounds__(256) void k_spp(const float* __restrict__ frames,
                                             const float* __restrict__ Wf,
                                             const float* __restrict__ bf,
                                             float* __restrict__ out_pooled,
                                             float* __restrict__ out_fpooled) {
    __shared__ float sF[3 * 48 * 48];
    __shared__ float sL4[48];
    __shared__ float sP[90];
    const int n = blockIdx.x, t = threadIdx.x;
    const float4* src = reinterpret_cast<const float4*>(frames + (size_t)n * 6912);
    float4* dst = reinterpret_cast<float4*>(sF);
    #pragma unroll
    for (int i = t; i < 1728; i += 256) dst[i] = src[i];
    __syncthreads();
    {
        int og = t >> 2, sub = t & 3;
        bool act = (og < 48);
        float m = -1e30f;
        if (act) {
            int c = og >> 4, rem = og & 15, i = rem >> 2, j = rem & 3;
            const float* base = sF + c * 2304 + (i * 12 + sub * 3) * 48 + j * 12;
            #pragma unroll
            for (int r = 0; r < 3; r++)
                #pragma unroll
                for (int q = 0; q < 12; q++) m = fmaxf(m, base[r * 48 + q]);
        }
        m = fmaxf(m, __shfl_xor_sync(0xffffffffu, m, 1));
        m = fmaxf(m, __shfl_xor_sync(0xffffffffu, m, 2));
        if (act && sub == 0) { sL4[og] = m; sP[og] = m; }
    }
    {
        int og = t >> 3, sub = t & 7;
        bool act = (og < 27);
        float m = -1e30f;
        if (act) {
            int c = og / 9, rem = og % 9, i = rem / 3, j = rem % 3;
            const float* base = sF + c * 2304 + (i * 16 + sub * 2) * 48 + j * 16;
            #pragma unroll
            for (int r = 0; r < 2; r++)
                #pragma unroll
                for (int q = 0; q < 16; q++) m = fmaxf(m, base[r * 48 + q]);
        }
        m = fmaxf(m, __shfl_xor_sync(0xffffffffu, m, 1));
        m = fmaxf(m, __shfl_xor_sync(0xffffffffu, m, 2));
        m = fmaxf(m, __shfl_xor_sync(0xffffffffu, m, 4));
        if (act && sub == 0) sP[48 + og] = m;
    }
    __syncthreads();
    if (t < 12) {
        int c = t >> 2, rem = t & 3, i = rem >> 1, j = rem & 1;
        const float* L = sL4 + c * 16;
        float m = fmaxf(fmaxf(L[(2 * i) * 4 + 2 * j], L[(2 * i) * 4 + 2 * j + 1]),
                        fmaxf(L[(2 * i + 1) * 4 + 2 * j], L[(2 * i + 1) * 4 + 2 * j + 1]));
        sP[75 + t] = m;
    } else if (t < 15) {
        int c = t - 12;
        float m = -1e30f;
        #pragma unroll
        for (int q = 0; q < 16; q++) m = fmaxf(m, sL4[c * 16 + q]);
        sP[87 + c] = m;
    }
    __syncthreads();
    if (t < 90) {
        float v = sP[t];
        out_pooled[(size_t)n * 90 + t] = v;
        float a0 = bf[t], a1 = 0.f;
        const float* wr = Wf + t * 90;
        #pragma unroll
        for (int k = 0; k < 90; k += 2) {
            a0 = fmaf(sP[k], wr[k], a0);
            a1 = fmaf(sP[k + 1], wr[k + 1], a1);
        }
        float acc = a0 + a1;
        out_fpooled[(size_t)n * 90 + t] = acc;
        __nv_bfloat16 h, l;
        split_bf16(v, h, l);
        gA1h[(size_t)n * 96 + t] = h;
        gA1l[(size_t)n * 96 + t] = l;
        split_bf16(acc, h, l);
        gA1h[(size_t)(NF + n) * 96 + t] = h;
        gA1l[(size_t)(NF + n) * 96 + t] = l;
    } else if (t < 96) {
        __nv_bfloat16 z = __float2bfloat16(0.f);
        gA1h[(size_t)n * 96 + t] = z;
        gA1l[(size_t)n * 96 + t] = z;
        gA1h[(size_t)(NF + n) * 96 + t] = z;
        gA1l[(size_t)(NF + n) * 96 + t] = z;
    }
}

// ============== prep kernels ==============
__global__ __launch_bounds__(256) void k_prepW1(const float* __restrict__ W1) {
    int r = blockIdx.x * 8 + (threadIdx.x >> 5);
    int lane = threadIdx.x & 31;
    const float* src = W1 + (size_t)r * 90;
    #pragma unroll
    for (int it = 0; it < 3; it++) {
        int k = it * 32 + lane;
        float x = (k < 90) ? src[k] : 0.f;
        __nv_bfloat16 h, l;
        split_bf16(x, h, l);
        gW1h[(size_t)r * 96 + k] = h;
        gW1l[(size_t)r * 96 + k] = l;
    }
}
__global__ __launch_bounds__(256) void k_prepB2(const float* __restrict__ F) {
    for (int i = blockIdx.x * 256 + threadIdx.x; i < 64 * EDIM; i += gridDim.x * 256) {
        __nv_bfloat16 h, l;
        split_bf16(F[i], h, l);
        gB2h[i] = h;
        gB2l[i] = l;
    }
}

// ============== GEMM1: hid = relu(P@W1^T + b1) -> bf16 hi/lo  (512 thr / 16 warps) ==============
#define G1_LDA 104
#define G1_SMEM (4 * 128 * G1_LDA * 2)
__global__ __launch_bounds__(512) void k_g1(const float* __restrict__ b1) {
    extern __shared__ __align__(16) char sm1[];
    __nv_bfloat16* sAhi = (__nv_bfloat16*)sm1;
    __nv_bfloat16* sAlo = sAhi + 128 * G1_LDA;
    __nv_bfloat16* sBhi = sAlo + 128 * G1_LDA;
    __nv_bfloat16* sBlo = sBhi + 128 * G1_LDA;
    __shared__ float sBias[128];
    const int t = threadIdx.x, lane = t & 31, wid = t >> 5;
    const int rb = blockIdx.y * 128, jb = blockIdx.x * 128;

    if (t < 128) sBias[t] = b1[jb + t];
    #pragma unroll
    for (int i = t; i < 1536; i += 512) {
        int r = i / 12, c8 = (i % 12) * 8;
        *(uint4*)(sAhi + r * G1_LDA + c8) = *(const uint4*)(gA1h + (size_t)(rb + r) * 96 + c8);
        *(uint4*)(sAlo + r * G1_LDA + c8) = *(const uint4*)(gA1l + (size_t)(rb + r) * 96 + c8);
        *(uint4*)(sBhi + r * G1_LDA + c8) = *(const uint4*)(gW1h + (size_t)(jb + r) * 96 + c8);
        *(uint4*)(sBlo + r * G1_LDA + c8) = *(const uint4*)(gW1l + (size_t)(jb + r) * 96 + c8);
    }
    __syncthreads();

    const int wm = wid >> 2, wn = wid & 3;   // 4x4 warp grid, 32x32 tiles
    float acc[2][4][4];
    #pragma unroll
    for (int mi = 0; mi < 2; mi++)
        #pragma unroll
        for (int nt = 0; nt < 4; nt++)
            #pragma unroll
            for (int q = 0; q < 4; q++) acc[mi][nt][q] = 0.f;

    const uint32_t uAhi = smem_to_u32(sAhi), uAlo = smem_to_u32(sAlo);
    const uint32_t uBhi = smem_to_u32(sBhi), uBlo = smem_to_u32(sBlo);
    const int j = lane >> 3;
    const uint32_t aRowOff = (uint32_t)((wm * 32 + (lane & 15)) * G1_LDA + ((lane >> 4) << 3)) * 2;
    const uint32_t bRowOff = (uint32_t)((wn * 32 + ((j >> 1) << 3) + (lane & 7)) * G1_LDA + ((j & 1) << 3)) * 2;

    #pragma unroll
    for (int pass = 0; pass < 3; pass++) {
        const uint32_t aBase = ((pass == 1) ? uAlo : uAhi) + aRowOff;
        const uint32_t bBase = ((pass == 2) ? uBlo : uBhi) + bRowOff;
        #pragma unroll
        for (int kk = 0; kk < 6; kk++) {
            uint32_t a[2][4];
            ldsm4(a[0], aBase + kk * 32);
            ldsm4(a[1], aBase + (16 * G1_LDA * 2) + kk * 32);
            #pragma unroll
            for (int nt2 = 0; nt2 < 2; nt2++) {
                uint32_t b[4];
                ldsm4(b, bBase + (uint32_t)(nt2 * 16 * G1_LDA * 2) + kk * 32);
                mma_bf16(acc[0][nt2 * 2],     a[0], b);
                mma_bf16(acc[0][nt2 * 2 + 1], a[0], b + 2);
                mma_bf16(acc[1][nt2 * 2],     a[1], b);
                mma_bf16(acc[1][nt2 * 2 + 1], a[1], b + 2);
            }
        }
    }
    __syncthreads();

    float* stage = (float*)sm1;   // [128][132]
    const int g = lane >> 2, i2 = (lane & 3) * 2;
    #pragma unroll
    for (int mi = 0; mi < 2; mi++)
        #pragma unroll
        for (int nt = 0; nt < 4; nt++) {
            int row = wm * 32 + mi * 16 + g;
            int col = wn * 32 + nt * 8 + i2;
            stage[row * 132 + col]           = fmaxf(acc[mi][nt][0] + sBias[col], 0.f);
            stage[row * 132 + col + 1]       = fmaxf(acc[mi][nt][1] + sBias[col + 1], 0.f);
            stage[(row + 8) * 132 + col]     = fmaxf(acc[mi][nt][2] + sBias[col], 0.f);
            stage[(row + 8) * 132 + col + 1] = fmaxf(acc[mi][nt][3] + sBias[col + 1], 0.f);
        }
    __syncthreads();
    for (int i = t; i < 2048; i += 512) {
        int r = i >> 4, c8 = (i & 15) << 3;
        __nv_bfloat16 hb[8], lb[8];
        #pragma unroll
        for (int jj2 = 0; jj2 < 8; jj2++) split_bf16(stage[r * 132 + c8 + jj2], hb[jj2], lb[jj2]);
        size_t gi = (size_t)(rb + r) * EDIM + jb + c8;
        *(uint4*)(ghid_hi + gi) = *(uint4*)hb;
        *(uint4*)(ghid_lo + gi) = *(uint4*)lb;
    }
}

// ============== GEMM2: emb = relu(hid@fc7^T + b7)  (512 thr / 16 warps, cp.async K-chunk 128) ==============
#define G2_LDA 136
#define G2_BUF 104448
#define G2_SMEM (2 * G2_BUF)
__global__ __launch_bounds__(512) void k_g2(const float* __restrict__ b7) {
    extern __shared__ __align__(16) char sm2[];
    __shared__ float sBias[64];
    const int t = threadIdx.x, lane = t & 31, wid = t >> 5;
    const int rb = blockIdx.x * 128;
    if (t < 64) sBias[t] = b7[t];

    const uint32_t ubase = smem_to_u32(sm2);
    const int wm = wid >> 1, wn = wid & 1;   // 8x2 warp grid, 16x32 tiles
    float acc[4][4];
    #pragma unroll
    for (int nt = 0; nt < 4; nt++)
        #pragma unroll
        for (int q = 0; q < 4; q++) acc[nt][q] = 0.f;

    const int j = lane >> 3;
    const uint32_t aRowOff = (uint32_t)((wm * 16 + (lane & 15)) * G2_LDA + ((lane >> 4) << 3)) * 2;
    const uint32_t bRowOff = (uint32_t)((wn * 32 + ((j >> 1) << 3) + (lane & 7)) * G2_LDA + ((j & 1) << 3)) * 2;

    auto load_chunk = [&](int c, int buf) {
        const int kc = c << 7;
        const uint32_t bb = ubase + buf * G2_BUF;
        #pragma unroll
        for (int i = t; i < 4096; i += 512) {
            int arr = i >> 11, idx = i & 2047;
            int r = idx >> 4, c8 = (idx & 15) << 3;
            const __nv_bfloat16* g = (arr ? ghid_lo : ghid_hi) + (size_t)(rb + r) * EDIM + kc + c8;
            cp_async16(bb + (uint32_t)(arr * 34816) + (uint32_t)(r * G2_LDA + c8) * 2, g);
        }
        #pragma unroll
        for (int i = t; i < 2048; i += 512) {
            int arr = i >> 10, idx = i & 1023;
            int n = idx >> 4, c8 = (idx & 15) << 3;
            const __nv_bfloat16* g = (arr ? gB2l : gB2h) + (size_t)n * EDIM + kc + c8;
            cp_async16(bb + 69632u + (uint32_t)(arr * 17408) + (uint32_t)(n * G2_LDA + c8) * 2, g);
        }
    };

    load_chunk(0, 0);
    CP_COMMIT();

    for (int c = 0; c < 32; c++) {
        if (c + 1 < 32) {
            load_chunk(c + 1, (c + 1) & 1);
            CP_COMMIT();
            asm volatile("cp.async.wait_group 1;" ::: "memory");
        } else {
            asm volatile("cp.async.wait_group 0;" ::: "memory");
        }
        __syncthreads();
        const uint32_t bb = ubase + (c & 1) * G2_BUF;
        const uint32_t uAhi = bb, uAlo = bb + 34816u, uBhi = bb + 69632u, uBlo = bb + 87040u;
        #pragma unroll
        for (int pass = 0; pass < 3; pass++) {
            const uint32_t aBase = ((pass == 1) ? uAlo : uAhi) + aRowOff;
            const uint32_t bBase = ((pass == 2) ? uBlo : uBhi) + bRowOff;
            #pragma unroll
            for (int kk = 0; kk < 8; kk++) {
                uint32_t a[4];
                ldsm4(a, aBase + kk * 32);
                #pragma unroll
                for (int nt2 = 0; nt2 < 2; nt2++) {
                    uint32_t b[4];
                    ldsm4(b, bBase + (uint32_t)(nt2 * 16 * G2_LDA * 2) + kk * 32);
                    mma_bf16(acc[nt2 * 2],     a, b);
                    mma_bf16(acc[nt2 * 2 + 1], a, b + 2);
                }
            }
        }
        __syncthreads();
    }

    float* stage = (float*)sm2;   // [128][68]
    const int g = lane >> 2, i2 = (lane & 3) * 2;
    #pragma unroll
    for (int nt = 0; nt < 4; nt++) {
        int row = wm * 16 + g;
        int col = wn * 32 + nt * 8 + i2;
        stage[row * 68 + col]           = fmaxf(acc[nt][0] + sBias[col], 0.f);
        stage[row * 68 + col + 1]       = fmaxf(acc[nt][1] + sBias[col + 1], 0.f);
        stage[(row + 8) * 68 + col]     = fmaxf(acc[nt][2] + sBias[col], 0.f);
        stage[(row + 8) * 68 + col + 1] = fmaxf(acc[nt][3] + sBias[col + 1], 0.f);
    }
    __syncthreads();
    for (int i = t; i < 2048; i += 512) {
        int r = i >> 4, c4 = (i & 15) << 2;
        *(float4*)&g_emb[(size_t)(rb + r) * 64 + c4] = *(float4*)&stage[r * 68 + c4];
    }
}

// ============== k_x (unchanged) ==============
__global__ __launch_bounds__(256) void k_x(const float* __restrict__ wih,
                                           const float* __restrict__ bih,
                                           const float* __restrict__ bhh) {
    extern __shared__ float smx[];
    float* sAT = smx;
    float* sWT = smx + 64 * 68;
    const int t = threadIdx.x;
    const int rb = blockIdx.y * 64;
    const int jb = blockIdx.x * 128;
    #pragma unroll
    for (int i = t; i < 1024; i += 256) {
        int q = i >> 6, r = i & 63;
        float4 v = *reinterpret_cast<const float4*>(&g_emb[(size_t)(rb + r) * 64 + q * 4]);
        sAT[(q * 4 + 0) * 68 + r] = v.x;
        sAT[(q * 4 + 1) * 68 + r] = v.y;
        sAT[(q * 4 + 2) * 68 + r] = v.z;
        sAT[(q * 4 + 3) * 68 + r] = v.w;
    }
    #pragma unroll
    for (int i = t; i < 2048; i += 256) {
        int kq = i >> 7, j = i & 127;
        float4 v = *reinterpret_cast<const float4*>(&wih[(size_t)(jb + j) * 64 + kq * 4]);
        sWT[(kq * 4 + 0) * 128 + j] = v.x;
        sWT[(kq * 4 + 1) * 128 + j] = v.y;
        sWT[(kq * 4 + 2) * 128 + j] = v.z;
        sWT[(kq * 4 + 3) * 128 + j] = v.w;
    }
    __syncthreads();
    const int jj = t & 31, rr = t >> 5;
    const int j = jj * 4, r0 = rr * 8;
    unsigned long long acc[4][4];
    #pragma unroll
    for (int p = 0; p < 4; p++)
        #pragma unroll
        for (int q = 0; q < 4; q++) acc[p][q] = 0ULL;
    #pragma unroll 16
    for (int k = 0; k < 64; k++) {
        const ulonglong2* pa = reinterpret_cast<const ulonglong2*>(sAT + k * 68 + r0);
        ulonglong2 a01 = pa[0], a23 = pa[1];
        unsigned long long a[4] = {a01.x, a01.y, a23.x, a23.y};
        float4 wv = *reinterpret_cast<const float4*>(sWT + k * 128 + j);
        unsigned long long w[4] = {pack2(wv.x), pack2(wv.y), pack2(wv.z), pack2(wv.w)};
        #pragma unroll
        for (int p = 0; p < 4; p++)
            #pragma unroll
            for (int q = 0; q < 4; q++) acc[p][q] = ffma2(a[p], w[q], acc[p][q]);
    }
    float4 bi = *reinterpret_cast<const float4*>(&bih[jb + j]);
    float4 bh = *reinterpret_cast<const float4*>(&bhh[jb + j]);
    float4 bv = make_float4(bi.x + bh.x, bi.y + bh.y, bi.z + bh.z, bi.w + bh.w);
    #pragma unroll
    for (int p = 0; p < 4; p++) {
        float x0, y0, x1, y1, x2, y2, x3, y3;
        unpack2(acc[p][0], x0, y0);
        unpack2(acc[p][1], x1, y1);
        unpack2(acc[p][2], x2, y2);
        unpack2(acc[p][3], x3, y3);
        float4 rA = make_float4(x0 + bv.x, x1 + bv.y, x2 + bv.z, x3 + bv.w);
        float4 rB = make_float4(y0 + bv.x, y1 + bv.y, y2 + bv.z, y3 + bv.w);
        int rowA = rb + r0 + 2 * p;
        int rowB = rowA + 1;
        {
            int branch = rowA >> 13, n = rowA & 8191, b = n >> 9, s = n & 511;
            size_t dst = ((size_t)branch * NF + (size_t)s * 16 + b) * 256 + jb + j;
            *reinterpret_cast<float4*>(&g_X[dst]) = rA;
        }
        {
            int branch = rowB >> 13, n = rowB & 8191, b = n >> 9, s = n & 511;
            size_t dst = ((size_t)branch * NF + (size_t)s * 16 + b) * 256 + jb + j;
            *reinterpret_cast<float4*>(&g_X[dst]) = rB;
        }
    }
}

// ============== k_lstm (quad-gate mapping, 2 syncs/step) ==============
__global__ __launch_bounds__(256) void k_lstm(const float* __restrict__ whh1,
                                              const float* __restrict__ wih2,
                                              const float* __restrict__ whh2,
                                              const float* __restrict__ bih2,
                                              const float* __restrict__ bhh2) {
    __shared__ __align__(16) float sxin[192];
    const int b = blockIdx.x, t = threadIdx.x;
    const int u = t >> 2, q = t & 3;
    const int gi = q * 64 + u;

    float w1[64];
    #pragma unroll
    for (int k = 0; k < 64; k++) w1[k] = whh1[gi * 64 + k];

    const int v = (t >> 2) & 31;
    const int gi2 = q * 32 + v;
    float w2i[64], w2h[32];
    float b2 = 0.f;
    if (t < 128) {
        #pragma unroll
        for (int k = 0; k < 64; k++) w2i[k] = wih2[gi2 * 64 + k];
        #pragma unroll
        for (int k = 0; k < 32; k++) w2h[k] = whh2[gi2 * 32 + k];
        b2 = bih2[gi2] + bhh2[gi2];
    }

    float c1 = 0.f, c2 = 0.f;
    if (t < 192) sxin[t] = 0.f;
    __syncthreads();

    const float* xbase = g_X + (size_t)b * 256;
    float xg = xbase[gi];
    const int lanebase = t & ~3;

    for (int s = 0; s < 512; s++) {
        float xn = (s < 511) ? xbase[(size_t)(s + 1) * 4096 + gi] : 0.f;
        const int p = s & 1;
        const float4* h1rd = (const float4*)(sxin + 64 * p);
        const float4* h1nw = (const float4*)(sxin + 64 * (1 - p));
        const float4* h2rd = (const float4*)(sxin + 128 + 32 * p);

        float a0 = xg, a1 = 0.f, a2 = 0.f, a3 = 0.f;
        #pragma unroll
        for (int k = 0; k < 16; k++) {
            float4 hv = h1rd[k];
            a0 = fmaf(hv.x, w1[4 * k],     a0);
            a1 = fmaf(hv.y, w1[4 * k + 1], a1);
            a2 = fmaf(hv.z, w1[4 * k + 2], a2);
            a3 = fmaf(hv.w, w1[4 * k + 3], a3);
        }
        float av = (a0 + a1) + (a2 + a3);
        float gv = (q == 2) ? tanh_f(av) : sigf(av);
        float vi = __shfl_sync(0xffffffffu, gv, lanebase);
        float vf = __shfl_sync(0xffffffffu, gv, lanebase + 1);
        float vg = __shfl_sync(0xffffffffu, gv, lanebase + 2);
        float vo = __shfl_sync(0xffffffffu, gv, lanebase + 3);
        if (q == 0) {
            c1 = vf * c1 + vi * vg;
            float h1v = vo * tanh_f(c1);
            sxin[64 * (1 - p) + u] = h1v;
            g_H1[((size_t)s * 16 + b) * 64 + u] = h1v;
            g_C1[((size_t)s * 16 + b) * 64 + u] = c1;
        }
        __syncthreads();

        if (t < 128) {
            float p0 = b2, p1 = 0.f, p2 = 0.f, p3 = 0.f;
            #pragma unroll
            for (int k = 0; k < 16; k++) {
                float4 hv = h1nw[k];
                p0 = fmaf(hv.x, w2i[4 * k],     p0);
                p1 = fmaf(hv.y, w2i[4 * k + 1], p1);
                p2 = fmaf(hv.z, w2i[4 * k + 2], p2);
                p3 = fmaf(hv.w, w2i[4 * k + 3], p3);
            }
            #pragma unroll
            for (int k = 0; k < 8; k++) {
                float4 hv = h2rd[k];
                p0 = fmaf(hv.x, w2h[4 * k],     p0);
                p1 = fmaf(hv.y, w2h[4 * k + 1], p1);
                p2 = fmaf(hv.z, w2h[4 * k + 2], p2);
                p3 = fmaf(hv.w, w2h[4 * k + 3], p3);
            }
            float pv = (p0 + p1) + (p2 + p3);
            float g2v = (q == 2) ? tanh_f(pv) : sigf(pv);
            float wi = __shfl_sync(0xffffffffu, g2v, lanebase);
            float wf = __shfl_sync(0xffffffffu, g2v, lanebase + 1);
            float wg = __shfl_sync(0xffffffffu, g2v, lanebase + 2);
            float wo = __shfl_sync(0xffffffffu, g2v, lanebase + 3);
            if (q == 0) {
                c2 = wf * c2 + wi * wg;
                float h2v = wo * tanh_f(c2);
                sxin[128 + 32 * (1 - p) + v] = h2v;
                g_H2[((size_t)s * 16 + b) * 32 + v] = h2v;
                g_C2[((size_t)s * 16 + b) * 32 + v] = c2;
            }
        }
        xg = xn;
        __syncthreads();
    }
}

// ============== k_f (unchanged) ==============
__global__ __launch_bounds__(256) void k_f(const float* __restrict__ whh1,
                                           const float* __restrict__ wih2,
                                           const float* __restrict__ whh2,
                                           const float* __restrict__ bih2,
                                           const float* __restrict__ bhh2,
                                           const float* __restrict__ fc8w,
                                           const float* __restrict__ fc8b,
                                           float* __restrict__ out_prog,
                                           float* __restrict__ out_fprog) {
    extern __shared__ float smf[];
    float* w1T  = smf;
    float* wi2T = w1T + 64 * 256;
    float* wh2T = wi2T + 64 * 128;
    float* b2s  = wh2T + 32 * 128;
    float* sH1  = b2s + 128;
    float* sC1  = sH1 + 1024;
    float* sH2  = sC1 + 1024;
    float* sC2  = sH2 + 512;
    float* sG1  = sC2 + 512;
    float* sFh1 = sG1 + 4096;
    float* sG2  = sFh1 + 1024;
    float* sFh2 = sG2 + 2048;
    const int t = threadIdx.x;
    const int s = blockIdx.x;
    const size_t r0 = (size_t)s * 16;
    for (int i = t; i < 64 * 256; i += 256) {
        int k = i >> 8, g = i & 255;
        w1T[i] = whh1[g * 64 + k];
    }
    for (int i = t; i < 64 * 128; i += 256) {
        int k = i >> 7, g = i & 127;
        wi2T[i] = wih2[g * 64 + k];
    }
    for (int i = t; i < 32 * 128; i += 256) {
        int k = i >> 7, g = i & 127;
        wh2T[i] = whh2[g * 32 + k];
    }
    if (t < 128) b2s[t] = bih2[t] + bhh2[t];
    for (int i = t; i < 1024; i += 256) sH1[i] = g_H1[r0 * 64 + i];
    for (int i = t; i < 1024; i += 256) sC1[i] = g_C1[r0 * 64 + i];
    for (int i = t; i < 512;  i += 256) sH2[i] = g_H2[r0 * 32 + i];
    for (int i = t; i < 512;  i += 256) sC2[i] = g_C2[r0 * 32 + i];
    for (int i = t; i < 4096; i += 256) sG1[i] = g_X[(size_t)NF * 256 + r0 * 256 + i];
    __syncthreads();
    {
        float acc[16];
        #pragma unroll
        for (int r = 0; r < 16; r++) acc[r] = sG1[r * 256 + t];
        #pragma unroll 8
        for (int k = 0; k < 64; k++) {
            float w = w1T[k * 256 + t];
            #pragma unroll
            for (int r = 0; r < 16; r++) acc[r] = fmaf(sH1[r * 64 + k], w, acc[r]);
        }
        bool is_g = ((t >> 6) == 2);
        #pragma unroll
        for (int r = 0; r < 16; r++)
            sG1[r * 256 + t] = is_g ? tanhf(acc[r]) : sigf(acc[r]);
    }
    __syncthreads();
    for (int i = t; i < 1024; i += 256) {
        int r = i >> 6, u = i & 63;
        const float* g = sG1 + r * 256;
        float c = g[64 + u] * sC1[r * 64 + u] + g[u] * g[128 + u];
        sFh1[r * 64 + u] = g[192 + u] * tanhf(c);
    }
    __syncthreads();
    if (t < 128) {
        float acc[16];
        #pragma unroll
        for (int r = 0; r < 16; r++) acc[r] = b2s[t];
        #pragma unroll 8
        for (int k = 0; k < 64; k++) {
            float w = wi2T[k * 128 + t];
            #pragma unroll
            for (int r = 0; r < 16; r++) acc[r] = fmaf(sFh1[r * 64 + k], w, acc[r]);
        }
        #pragma unroll 8
        for (int k = 0; k < 32; k++) {
            float w = wh2T[k * 128 + t];
            #pragma unroll
            for (int r = 0; r < 16; r++) acc[r] = fmaf(sH2[r * 32 + k], w, acc[r]);
        }
        bool is_g = ((t >> 5) == 2);
        #pragma unroll
        for (int r = 0; r < 16; r++)
            sG2[r * 128 + t] = is_g ? tanhf(acc[r]) : sigf(acc[r]);
    }
    __syncthreads();
    for (int i = t; i < 512; i += 256) {
        int r = i >> 5, u = i & 31;
        const float* g = sG2 + r * 128;
        float c = g[32 + u] * sC2[r * 32 + u] + g[u] * g[64 + u];
        sFh2[r * 32 + u] = g[96 + u] * tanhf(c);
    }
    __syncthreads();
    if (t < 32) {
        int r = t >> 1, which = t & 1;
        const float* v = which ? (sFh2 + r * 32) : (sH2 + r * 32);
        float acc = fc8b[0];
        #pragma unroll
        for (int k = 0; k < 32; k++) acc = fmaf(v[k], fc8w[k], acc);
        float ov = sigf(acc);
        int b = r;
        if (which) out_fprog[(size_t)b * 512 + s] = ov;
        else       out_prog[(size_t)b * 512 + s] = ov;
    }
}

// =====================================================================
extern "C" void kernel_launch(void* const* d_in, const int* in_sizes, int n_in,
                              void* d_out, int out_size) {
    const float* frames  = (const float*)d_in[0];
    const float* spp_w   = (const float*)d_in[1];
    const float* spp_b   = (const float*)d_in[2];
    const float* fore_w  = (const float*)d_in[3];
    const float* fore_b  = (const float*)d_in[4];
    const float* fc7_w   = (const float*)d_in[5];
    const float* fc7_b   = (const float*)d_in[6];
    const float* l1_wih  = (const float*)d_in[7];
    const float* l1_whh  = (const float*)d_in[8];
    const float* l1_bih  = (const float*)d_in[9];
    const float* l1_bhh  = (const float*)d_in[10];
    const float* l2_wih  = (const float*)d_in[11];
    const float* l2_whh  = (const float*)d_in[12];
    const float* l2_bih  = (const float*)d_in[13];
    const float* l2_bhh  = (const float*)d_in[14];
    const float* fc8_w   = (const float*)d_in[15];
    const float* fc8_b   = (const float*)d_in[16];

    float* out         = (float*)d_out;
    float* out_prog    = out;
    float* out_fprog   = out + 8192;
    float* out_pooled  = out + 16384;
    float* out_fpooled = out + 16384 + 737280;

    const int smem_x = (64 * 68 + 64 * 128) * 4;
    const int smem_f = (64 * 256 + 64 * 128 + 32 * 128 + 128 +
                        1024 + 1024 + 512 + 512 + 4096 + 1024 + 2048 + 512) * 4;
    cudaFuncSetAttribute(k_g1, cudaFuncAttributeMaxDynamicSharedMemorySize, G1_SMEM);
    cudaFuncSetAttribute(k_g2, cudaFuncAttributeMaxDynamicSharedMemorySize, G2_SMEM);
    cudaFuncSetAttribute(k_x,  cudaFuncAttributeMaxDynamicSharedMemorySize, smem_x);
    cudaFuncSetAttribute(k_f,  cudaFuncAttributeMaxDynamicSharedMemorySize, smem_f);

    k_spp<<<NF, 256>>>(frames, fore_w, fore_b, out_pooled, out_fpooled);
    k_prepW1<<<EDIM / 8, 256>>>(spp_w);
    k_prepB2<<<64, 256>>>(fc7_w);
    k_g1<<<dim3(32, 128), 512, G1_SMEM>>>(spp_b);
    k_g2<<<128, 512, G2_SMEM>>>(fc7_b);
    k_x<<<dim3(2, 256), 256, smem_x>>>(l1_wih, l1_bih, l1_bhh);
    k_lstm<<<16, 256>>>(l1_whh, l2_wih, l2_whh, l2_bih, l2_bhh);
    k_f<<<512, 256, smem_f>>>(l1_whh, l2_wih, l2_whh, l2_bih, l2_bhh, fc8_w, fc8_b,
                              out_prog, out_fprog);
}